// round 1
// baseline (speedup 1.0000x reference)
#include <cuda_runtime.h>
#include <cuda_bf16.h>
#include <math.h>

// Problem constants (fixed-shape problem)
#define NN 100000          // nodes
#define NE 3200000         // edges
#define F0 256             // in feats
#define F1 32              // hidden
#define F2 40              // out feats
#define CHUNK 1024
#define NB ((NN + CHUNK - 1) / CHUNK)   // 98 scan chunks

// ---------------- scratch (static device globals; no runtime alloc) -------
__device__ int   g_deg_out[NN];
__device__ int   g_deg_in[NN];
__device__ float g_inv_out[NN];
__device__ float g_inv_in[NN];
__device__ int   g_rowptr[NN + 1];
__device__ int   g_cursor[NN];
__device__ int   g_chunksum[128];
__device__ int   g_chunkoff[128];
__device__ int   g_esrc[NE];
__device__ float g_h1[NN * F1];   // (x*inv_out)@W1
__device__ float g_hs[NN * F1];   // relu(agg1*inv_in+b1)*inv_out
__device__ float g_t2[NN * F2];   // hs@W2

// ---------------- kernels -------------------------------------------------

__global__ void zero_kernel() {
    int i = blockIdx.x * blockDim.x + threadIdx.x;
    if (i < NN) { g_deg_out[i] = 0; g_deg_in[i] = 0; }
}

__global__ void degree_kernel(const int* __restrict__ src,
                              const int* __restrict__ dst) {
    int e = blockIdx.x * blockDim.x + threadIdx.x;
    if (e < NE) {
        atomicAdd(&g_deg_out[src[e]], 1);
        atomicAdd(&g_deg_in[dst[e]], 1);
    }
}

__global__ void inv_kernel() {
    int i = blockIdx.x * blockDim.x + threadIdx.x;
    if (i < NN) {
        float dout = (float)g_deg_out[i];
        float din  = (float)g_deg_in[i];
        g_inv_out[i] = rsqrtf(fmaxf(dout, 1.0f));
        g_inv_in[i]  = rsqrtf(fmaxf(din, 1.0f));
    }
}

// Per-chunk inclusive scan of deg_in -> exclusive into rowptr, chunk totals.
__global__ void scan1_kernel() {
    __shared__ int sm[CHUNK];
    int b = blockIdx.x, t = threadIdx.x;
    int i = b * CHUNK + t;
    int v = (i < NN) ? g_deg_in[i] : 0;
    sm[t] = v;
    __syncthreads();
    for (int o = 1; o < CHUNK; o <<= 1) {
        int add = (t >= o) ? sm[t - o] : 0;
        __syncthreads();
        sm[t] += add;
        __syncthreads();
    }
    if (i < NN) g_rowptr[i] = sm[t] - v;       // exclusive
    if (t == CHUNK - 1) g_chunksum[b] = sm[t]; // chunk total
}

// Scan of the chunk totals (single block).
__global__ void scan2_kernel() {
    __shared__ int sm[128];
    int t = threadIdx.x;
    int v = (t < NB) ? g_chunksum[t] : 0;
    sm[t] = v;
    __syncthreads();
    for (int o = 1; o < 128; o <<= 1) {
        int add = (t >= o) ? sm[t - o] : 0;
        __syncthreads();
        sm[t] += add;
        __syncthreads();
    }
    if (t < NB) g_chunkoff[t] = sm[t] - v;     // exclusive chunk offsets
}

// Add chunk offsets; init cursor; set rowptr[NN]=NE.
__global__ void scan3_kernel() {
    int i = blockIdx.x * blockDim.x + threadIdx.x;
    if (i < NN) {
        int r = g_rowptr[i] + g_chunkoff[i / CHUNK];
        g_rowptr[i] = r;
        g_cursor[i] = r;
    }
    if (i == 0) g_rowptr[NN] = NE;
}

// Bin edges by dst into g_esrc (CSR adjacency).
__global__ void bin_kernel(const int* __restrict__ src,
                           const int* __restrict__ dst) {
    int e = blockIdx.x * blockDim.x + threadIdx.x;
    if (e < NE) {
        int d = dst[e];
        int pos = atomicAdd(&g_cursor[d], 1);
        g_esrc[pos] = src[e];
    }
}

// h1 = (x * inv_out) @ W1 ; warp-per-row, W1 + x-row staged in smem.
__global__ void gemm1_kernel(const float* __restrict__ x,
                             const float* __restrict__ W1) {
    __shared__ float Ws[F0 * F1];          // 32 KB
    __shared__ float xs[8][F0];            // 8 KB
    for (int i = threadIdx.x; i < F0 * F1; i += blockDim.x) Ws[i] = W1[i];
    __syncthreads();
    int warp = threadIdx.x >> 5, lane = threadIdx.x & 31;
    for (int row = blockIdx.x * 8 + warp; row < NN; row += gridDim.x * 8) {
        const float4* xr = (const float4*)(x + (size_t)row * F0);
        float4* xw = (float4*)(&xs[warp][0]);
        xw[lane]      = xr[lane];
        xw[lane + 32] = xr[lane + 32];
        __syncwarp();
        float acc = 0.0f;
        #pragma unroll 16
        for (int k = 0; k < F0; k++)
            acc = fmaf(xs[warp][k], Ws[k * F1 + lane], acc);
        g_h1[row * F1 + lane] = acc * g_inv_out[row];
        __syncwarp();
    }
}

// agg1: warp-per-node gather of h1 rows, then relu(.*inv_in+b1)*inv_out.
__global__ void agg1_kernel(const float* __restrict__ b1) {
    int gw = (blockIdx.x * blockDim.x + threadIdx.x) >> 5;
    int lane = threadIdx.x & 31;
    if (gw >= NN) return;
    int s = g_rowptr[gw], e = g_rowptr[gw + 1];
    float a0 = 0.f, a1 = 0.f, a2 = 0.f, a3 = 0.f;
    int j = s;
    for (; j + 3 < e; j += 4) {
        int i0 = g_esrc[j], i1 = g_esrc[j + 1], i2 = g_esrc[j + 2], i3 = g_esrc[j + 3];
        a0 += g_h1[i0 * F1 + lane];
        a1 += g_h1[i1 * F1 + lane];
        a2 += g_h1[i2 * F1 + lane];
        a3 += g_h1[i3 * F1 + lane];
    }
    for (; j < e; j++) a0 += g_h1[g_esrc[j] * F1 + lane];
    float acc = (a0 + a1) + (a2 + a3);
    float v = acc * g_inv_in[gw] + b1[lane];
    v = v > 0.f ? v : 0.f;
    g_hs[gw * F1 + lane] = v * g_inv_out[gw];
}

// t2 = hs @ W2 ; thread-per-output-element, W2 in smem.
__global__ void gemm2_kernel(const float* __restrict__ W2) {
    __shared__ float Ws[F1 * F2];          // 5 KB
    for (int i = threadIdx.x; i < F1 * F2; i += blockDim.x) Ws[i] = W2[i];
    __syncthreads();
    int idx = blockIdx.x * blockDim.x + threadIdx.x;
    if (idx >= NN * F2) return;
    int row = idx / F2, c = idx - row * F2;
    const float* h = &g_hs[row * F1];
    float acc = 0.0f;
    #pragma unroll
    for (int k = 0; k < F1; k++)
        acc = fmaf(__ldg(h + k), Ws[k * F2 + c], acc);
    g_t2[idx] = acc;
}

// agg2 + bias + log_softmax fused; warp-per-node; lane covers f and f+32.
__global__ void agg2_kernel(const float* __restrict__ b2,
                            float* __restrict__ out) {
    int gw = (blockIdx.x * blockDim.x + threadIdx.x) >> 5;
    int lane = threadIdx.x & 31;
    if (gw >= NN) return;
    int s = g_rowptr[gw], e = g_rowptr[gw + 1];
    float a0 = 0.f, a1 = 0.f, c0 = 0.f, c1 = 0.f;
    int j = s;
    for (; j + 1 < e; j += 2) {
        const float* t  = &g_t2[g_esrc[j] * F2];
        const float* t2 = &g_t2[g_esrc[j + 1] * F2];
        a0 += t[lane];
        c0 += t2[lane];
        if (lane < 8) { a1 += t[32 + lane]; c1 += t2[32 + lane]; }
    }
    for (; j < e; j++) {
        const float* t = &g_t2[g_esrc[j] * F2];
        a0 += t[lane];
        if (lane < 8) a1 += t[32 + lane];
    }
    a0 += c0; a1 += c1;
    float inv = g_inv_in[gw];
    float v0 = a0 * inv + b2[lane];
    float v1 = (lane < 8) ? (a1 * inv + b2[32 + lane]) : -INFINITY;
    float m = fmaxf(v0, v1);
    #pragma unroll
    for (int o = 16; o; o >>= 1) m = fmaxf(m, __shfl_xor_sync(0xFFFFFFFFu, m, o));
    float sum = expf(v0 - m) + ((lane < 8) ? expf(v1 - m) : 0.0f);
    #pragma unroll
    for (int o = 16; o; o >>= 1) sum += __shfl_xor_sync(0xFFFFFFFFu, sum, o);
    float L = m + logf(sum);
    out[gw * F2 + lane] = v0 - L;
    if (lane < 8) out[gw * F2 + 32 + lane] = v1 - L;
}

// ---------------- launcher ------------------------------------------------

extern "C" void kernel_launch(void* const* d_in, const int* in_sizes, int n_in,
                              void* d_out, int out_size) {
    const float* x   = (const float*)d_in[0];
    const float* W1  = (const float*)d_in[1];
    const float* b1  = (const float*)d_in[2];
    const float* W2  = (const float*)d_in[3];
    const float* b2  = (const float*)d_in[4];
    const int*   src = (const int*)d_in[5];
    const int*   dst = (const int*)d_in[6];
    float* out = (float*)d_out;

    const int TB = 256;
    int gN  = (NN + TB - 1) / TB;           // node-sized grids
    int gE  = (NE + TB - 1) / TB;           // edge-sized grids
    int gWN = (NN * 32 + TB - 1) / TB;      // warp-per-node grids
    int gO2 = (NN * F2 + TB - 1) / TB;      // element grid for gemm2

    zero_kernel<<<gN, TB>>>();
    degree_kernel<<<gE, TB>>>(src, dst);
    inv_kernel<<<gN, TB>>>();
    scan1_kernel<<<NB, CHUNK>>>();
    scan2_kernel<<<1, 128>>>();
    scan3_kernel<<<gN, TB>>>();
    bin_kernel<<<gE, TB>>>(src, dst);

    gemm1_kernel<<<740, TB>>>(x, W1);
    agg1_kernel<<<gWN, TB>>>(b1);
    gemm2_kernel<<<gO2, TB>>>(W2);
    agg2_kernel<<<gWN, TB>>>(b2, out);
}

// round 2
// speedup vs baseline: 1.2838x; 1.2838x over previous
#include <cuda_runtime.h>
#include <cuda_bf16.h>
#include <math.h>

// Problem constants (fixed-shape problem)
#define NN 100000          // nodes
#define NE 3200000         // edges
#define F0 256             // in feats
#define F1 32              // hidden
#define F2 40              // out feats
#define CHUNK 1024
#define NB ((NN + CHUNK - 1) / CHUNK)   // 98 scan chunks
#define WT_STRIDE 260                   // 256 + 4 pad: conflict-free LDS.128
#define G1_GROUPS ((NN + 63) / 64)      // 1563 blocks, 64 rows/block

// ---------------- scratch (static device globals; no runtime alloc) -------
__device__ int   g_deg_out[NN];
__device__ int   g_deg_in[NN];
__device__ float g_inv_out[NN];
__device__ float g_inv_in[NN];
__device__ int   g_rowptr[NN + 1];
__device__ int   g_cursor[NN];
__device__ int   g_chunksum[128];
__device__ int   g_chunkoff[128];
__device__ int   g_esrc[NE];
__device__ float g_h1[NN * F1];   // (x*inv_out)@W1
__device__ float g_hs[NN * F1];   // relu(agg1*inv_in+b1)*inv_out

// ---------------- f32x2 packed helpers (sm_10x) ---------------------------
__device__ __forceinline__ unsigned long long pack2(float lo, float hi) {
    unsigned long long d;
    asm("mov.b64 %0, {%1, %2};" : "=l"(d)
        : "r"(__float_as_uint(lo)), "r"(__float_as_uint(hi)));
    return d;
}
__device__ __forceinline__ void fma2(unsigned long long& d,
                                     unsigned long long a,
                                     unsigned long long b) {
    asm("fma.rn.f32x2 %0, %1, %2, %0;" : "+l"(d) : "l"(a), "l"(b));
}
__device__ __forceinline__ float2 unpack2(unsigned long long v) {
    unsigned int lo, hi;
    asm("mov.b64 {%0, %1}, %2;" : "=r"(lo), "=r"(hi) : "l"(v));
    return make_float2(__uint_as_float(lo), __uint_as_float(hi));
}

// ---------------- kernels -------------------------------------------------

__global__ void zero_kernel() {
    int i = blockIdx.x * blockDim.x + threadIdx.x;
    if (i < NN) { g_deg_out[i] = 0; g_deg_in[i] = 0; }
}

__global__ void degree_kernel(const int* __restrict__ src,
                              const int* __restrict__ dst) {
    int e = blockIdx.x * blockDim.x + threadIdx.x;
    if (e < NE) {
        atomicAdd(&g_deg_out[src[e]], 1);
        atomicAdd(&g_deg_in[dst[e]], 1);
    }
}

__global__ void inv_kernel() {
    int i = blockIdx.x * blockDim.x + threadIdx.x;
    if (i < NN) {
        g_inv_out[i] = rsqrtf(fmaxf((float)g_deg_out[i], 1.0f));
        g_inv_in[i]  = rsqrtf(fmaxf((float)g_deg_in[i], 1.0f));
    }
}

__global__ void scan1_kernel() {
    __shared__ int sm[CHUNK];
    int b = blockIdx.x, t = threadIdx.x;
    int i = b * CHUNK + t;
    int v = (i < NN) ? g_deg_in[i] : 0;
    sm[t] = v;
    __syncthreads();
    for (int o = 1; o < CHUNK; o <<= 1) {
        int add = (t >= o) ? sm[t - o] : 0;
        __syncthreads();
        sm[t] += add;
        __syncthreads();
    }
    if (i < NN) g_rowptr[i] = sm[t] - v;
    if (t == CHUNK - 1) g_chunksum[b] = sm[t];
}

__global__ void scan2_kernel() {
    __shared__ int sm[128];
    int t = threadIdx.x;
    int v = (t < NB) ? g_chunksum[t] : 0;
    sm[t] = v;
    __syncthreads();
    for (int o = 1; o < 128; o <<= 1) {
        int add = (t >= o) ? sm[t - o] : 0;
        __syncthreads();
        sm[t] += add;
        __syncthreads();
    }
    if (t < NB) g_chunkoff[t] = sm[t] - v;
}

__global__ void scan3_kernel() {
    int i = blockIdx.x * blockDim.x + threadIdx.x;
    if (i < NN) {
        int r = g_rowptr[i] + g_chunkoff[i / CHUNK];
        g_rowptr[i] = r;
        g_cursor[i] = r;
    }
    if (i == 0) g_rowptr[NN] = NE;
}

__global__ void bin_kernel(const int* __restrict__ src,
                           const int* __restrict__ dst) {
    int e = blockIdx.x * blockDim.x + threadIdx.x;
    if (e < NE) {
        int d = dst[e];
        int pos = atomicAdd(&g_cursor[d], 1);
        g_esrc[pos] = src[e];
    }
}

// h1 = (x * inv_out) @ W1
// 8 warps/block, 8 rows/warp, f32x2 dual-FMA; Wt (transposed, padded) + x
// tiles in dynamic smem.
__global__ void gemm1_kernel(const float* __restrict__ x,
                             const float* __restrict__ W1) {
    extern __shared__ float sm[];
    float* Wt = sm;                         // [32][WT_STRIDE]
    float* xs = sm + F1 * WT_STRIDE;        // [8 warps][8 rows][256]
    int tid = threadIdx.x;
    for (int i = tid; i < F0 * F1; i += blockDim.x) {
        int k = i >> 5, c = i & 31;
        Wt[c * WT_STRIDE + k] = W1[i];
    }
    __syncthreads();
    int warp = tid >> 5, lane = tid & 31;
    float* xw = xs + warp * (8 * F0);
    int base = blockIdx.x * 64 + warp * 8;

    // stage 8 x-rows (clamped; OOB rows never stored)
    #pragma unroll
    for (int r = 0; r < 8; r++) {
        int row = base + r;
        if (row >= NN) row = NN - 1;
        const float4* xr = (const float4*)(x + (size_t)row * F0);
        float4* dstp = (float4*)(xw + r * F0);
        dstp[lane]      = xr[lane];
        dstp[lane + 32] = xr[lane + 32];
    }
    __syncwarp();

    unsigned long long acc0 = 0ull, acc1 = 0ull, acc2 = 0ull, acc3 = 0ull;
    const float* wrow = Wt + lane * WT_STRIDE;

    #pragma unroll 4
    for (int kq = 0; kq < F0 / 4; kq++) {
        float4 w4 = *(const float4*)(wrow + kq * 4);
        unsigned long long wd0 = pack2(w4.x, w4.x);
        unsigned long long wd1 = pack2(w4.y, w4.y);
        unsigned long long wd2 = pack2(w4.z, w4.z);
        unsigned long long wd3 = pack2(w4.w, w4.w);
        {
            float4 xa = *(const float4*)(xw + 0 * F0 + kq * 4);
            float4 xb = *(const float4*)(xw + 1 * F0 + kq * 4);
            fma2(acc0, wd0, pack2(xa.x, xb.x));
            fma2(acc0, wd1, pack2(xa.y, xb.y));
            fma2(acc0, wd2, pack2(xa.z, xb.z));
            fma2(acc0, wd3, pack2(xa.w, xb.w));
        }
        {
            float4 xa = *(const float4*)(xw + 2 * F0 + kq * 4);
            float4 xb = *(const float4*)(xw + 3 * F0 + kq * 4);
            fma2(acc1, wd0, pack2(xa.x, xb.x));
            fma2(acc1, wd1, pack2(xa.y, xb.y));
            fma2(acc1, wd2, pack2(xa.z, xb.z));
            fma2(acc1, wd3, pack2(xa.w, xb.w));
        }
        {
            float4 xa = *(const float4*)(xw + 4 * F0 + kq * 4);
            float4 xb = *(const float4*)(xw + 5 * F0 + kq * 4);
            fma2(acc2, wd0, pack2(xa.x, xb.x));
            fma2(acc2, wd1, pack2(xa.y, xb.y));
            fma2(acc2, wd2, pack2(xa.z, xb.z));
            fma2(acc2, wd3, pack2(xa.w, xb.w));
        }
        {
            float4 xa = *(const float4*)(xw + 6 * F0 + kq * 4);
            float4 xb = *(const float4*)(xw + 7 * F0 + kq * 4);
            fma2(acc3, wd0, pack2(xa.x, xb.x));
            fma2(acc3, wd1, pack2(xa.y, xb.y));
            fma2(acc3, wd2, pack2(xa.z, xb.z));
            fma2(acc3, wd3, pack2(xa.w, xb.w));
        }
    }

    unsigned long long accs[4] = {acc0, acc1, acc2, acc3};
    #pragma unroll
    for (int p = 0; p < 4; p++) {
        float2 v = unpack2(accs[p]);
        int r0 = base + 2 * p, r1 = r0 + 1;
        if (r0 < NN) g_h1[r0 * F1 + lane] = v.x * g_inv_out[r0];
        if (r1 < NN) g_h1[r1 * F1 + lane] = v.y * g_inv_out[r1];
    }
}

// agg1: warp-per-node gather of h1 rows, then relu(.*inv_in+b1)*inv_out.
__global__ void agg1_kernel(const float* __restrict__ b1) {
    int gw = (blockIdx.x * blockDim.x + threadIdx.x) >> 5;
    int lane = threadIdx.x & 31;
    if (gw >= NN) return;
    int s = g_rowptr[gw], e = g_rowptr[gw + 1];
    float a0 = 0.f, a1 = 0.f, a2 = 0.f, a3 = 0.f;
    int j = s;
    for (; j + 3 < e; j += 4) {
        int i0 = g_esrc[j], i1 = g_esrc[j + 1], i2 = g_esrc[j + 2], i3 = g_esrc[j + 3];
        a0 += g_h1[i0 * F1 + lane];
        a1 += g_h1[i1 * F1 + lane];
        a2 += g_h1[i2 * F1 + lane];
        a3 += g_h1[i3 * F1 + lane];
    }
    for (; j < e; j++) a0 += g_h1[g_esrc[j] * F1 + lane];
    float acc = (a0 + a1) + (a2 + a3);
    float v = acc * g_inv_in[gw] + b1[lane];
    v = v > 0.f ? v : 0.f;
    g_hs[gw * F1 + lane] = v * g_inv_out[gw];
}

// agg2 fused: aggregate hs at width 32 (linearity: agg(h@W2)=agg(h)@W2),
// then *inv_in, @W2 + b2, log_softmax, write out. Warp per node.
__global__ void agg2_kernel(const float* __restrict__ W2,
                            const float* __restrict__ b2,
                            float* __restrict__ out) {
    __shared__ float W2s[F1 * F2];   // 5 KB
    __shared__ float sa[8][F1];
    for (int i = threadIdx.x; i < F1 * F2; i += blockDim.x) W2s[i] = W2[i];
    __syncthreads();

    int gw = (blockIdx.x * blockDim.x + threadIdx.x) >> 5;
    int warp = threadIdx.x >> 5, lane = threadIdx.x & 31;
    if (gw >= NN) return;

    int s = g_rowptr[gw], e = g_rowptr[gw + 1];
    float a0 = 0.f, a1 = 0.f, a2 = 0.f, a3 = 0.f;
    int j = s;
    for (; j + 3 < e; j += 4) {
        int i0 = g_esrc[j], i1 = g_esrc[j + 1], i2 = g_esrc[j + 2], i3 = g_esrc[j + 3];
        a0 += g_hs[i0 * F1 + lane];
        a1 += g_hs[i1 * F1 + lane];
        a2 += g_hs[i2 * F1 + lane];
        a3 += g_hs[i3 * F1 + lane];
    }
    for (; j < e; j++) a0 += g_hs[g_esrc[j] * F1 + lane];
    float agg = ((a0 + a1) + (a2 + a3)) * g_inv_in[gw];
    sa[warp][lane] = agg;
    __syncwarp();

    float v0 = b2[lane];
    float v1 = (lane < 8) ? b2[32 + lane] : -INFINITY;
    #pragma unroll
    for (int k = 0; k < F1; k++) {
        float ak = sa[warp][k];
        v0 = fmaf(ak, W2s[k * F2 + lane], v0);
        if (lane < 8) v1 = fmaf(ak, W2s[k * F2 + 32 + lane], v1);
    }

    float m = fmaxf(v0, v1);
    #pragma unroll
    for (int o = 16; o; o >>= 1) m = fmaxf(m, __shfl_xor_sync(0xFFFFFFFFu, m, o));
    float sum = expf(v0 - m) + ((lane < 8) ? expf(v1 - m) : 0.0f);
    #pragma unroll
    for (int o = 16; o; o >>= 1) sum += __shfl_xor_sync(0xFFFFFFFFu, sum, o);
    float L = m + logf(sum);
    out[gw * F2 + lane] = v0 - L;
    if (lane < 8) out[gw * F2 + 32 + lane] = v1 - L;
}

// ---------------- launcher ------------------------------------------------

extern "C" void kernel_launch(void* const* d_in, const int* in_sizes, int n_in,
                              void* d_out, int out_size) {
    const float* x   = (const float*)d_in[0];
    const float* W1  = (const float*)d_in[1];
    const float* b1  = (const float*)d_in[2];
    const float* W2  = (const float*)d_in[3];
    const float* b2  = (const float*)d_in[4];
    const int*   src = (const int*)d_in[5];
    const int*   dst = (const int*)d_in[6];
    float* out = (float*)d_out;

    const int TB = 256;
    int gN  = (NN + TB - 1) / TB;
    int gE  = (NE + TB - 1) / TB;
    int gWN = (NN * 32 + TB - 1) / TB;

    int g1_smem = (F1 * WT_STRIDE + 8 * 8 * F0) * (int)sizeof(float);  // 98816 B
    cudaFuncSetAttribute(gemm1_kernel,
                         cudaFuncAttributeMaxDynamicSharedMemorySize, g1_smem);

    zero_kernel<<<gN, TB>>>();
    degree_kernel<<<gE, TB>>>(src, dst);
    inv_kernel<<<gN, TB>>>();
    scan1_kernel<<<NB, CHUNK>>>();
    scan2_kernel<<<1, 128>>>();
    scan3_kernel<<<gN, TB>>>();
    bin_kernel<<<gE, TB>>>(src, dst);

    gemm1_kernel<<<G1_GROUPS, TB, g1_smem>>>(x, W1);
    agg1_kernel<<<gWN, TB>>>(b1);
    agg2_kernel<<<gWN, TB>>>(W2, b2, out);
}

// round 4
// speedup vs baseline: 1.3465x; 1.0488x over previous
#include <cuda_runtime.h>
#include <cuda_fp16.h>
#include <cuda_bf16.h>
#include <math.h>

// Problem constants (fixed-shape problem)
#define NN 100000          // nodes
#define NE 3200000         // edges
#define F0 256             // in feats
#define F1 32              // hidden
#define F2 40              // out feats
#define CHUNK 1024
#define NB ((NN + CHUNK - 1) / CHUNK)   // 98 scan chunks
#define WT_STRIDE 260                   // 256 + 4 pad: conflict-free LDS.128
#define G1_GROUPS ((NN + 63) / 64)      // blocks, 64 rows/block

// ---------------- scratch (static device globals; no runtime alloc) -------
__device__ int     g_deg_out[NN];
__device__ int     g_deg_in[NN];
__device__ float   g_inv_out[NN];
__device__ float   g_inv_in[NN];
__device__ int     g_rowptr[NN + 1];
__device__ int     g_cursor[NN];
__device__ int     g_chunksum[128];
__device__ int     g_chunkoff[128];
__device__ int     g_esrc[NE];
__device__ __half2 g_h1[NN * 16];   // (x*inv_out)@W1, fp16 pairs (64B rows)
__device__ __half2 g_hs[NN * 16];   // relu(agg1*inv_in+b1)*inv_out, fp16 pairs

// ---------------- f32x2 packed helpers (sm_10x) ---------------------------
__device__ __forceinline__ unsigned long long pack2(float lo, float hi) {
    unsigned long long d;
    asm("mov.b64 %0, {%1, %2};" : "=l"(d)
        : "r"(__float_as_uint(lo)), "r"(__float_as_uint(hi)));
    return d;
}
__device__ __forceinline__ void fma2(unsigned long long& d,
                                     unsigned long long a,
                                     unsigned long long b) {
    asm("fma.rn.f32x2 %0, %1, %2, %0;" : "+l"(d) : "l"(a), "l"(b));
}
__device__ __forceinline__ float2 unpack2(unsigned long long v) {
    unsigned int lo, hi;
    asm("mov.b64 {%0, %1}, %2;" : "=r"(lo), "=r"(hi) : "l"(v));
    return make_float2(__uint_as_float(lo), __uint_as_float(hi));
}

// ---------------- kernels -------------------------------------------------

__global__ void zero_kernel() {
    int i = blockIdx.x * blockDim.x + threadIdx.x;
    if (i < NN) { g_deg_out[i] = 0; g_deg_in[i] = 0; }
}

__global__ void degree_kernel(const int* __restrict__ src,
                              const int* __restrict__ dst) {
    int e = blockIdx.x * blockDim.x + threadIdx.x;
    if (e < NE) {
        atomicAdd(&g_deg_out[src[e]], 1);
        atomicAdd(&g_deg_in[dst[e]], 1);
    }
}

// Per-chunk scan of deg_in; also computes inv_in.
__global__ void scan1_kernel() {
    __shared__ int sm[CHUNK];
    int b = blockIdx.x, t = threadIdx.x;
    int i = b * CHUNK + t;
    int v = (i < NN) ? g_deg_in[i] : 0;
    if (i < NN) g_inv_in[i] = rsqrtf(fmaxf((float)v, 1.0f));
    sm[t] = v;
    __syncthreads();
    for (int o = 1; o < CHUNK; o <<= 1) {
        int add = (t >= o) ? sm[t - o] : 0;
        __syncthreads();
        sm[t] += add;
        __syncthreads();
    }
    if (i < NN) g_rowptr[i] = sm[t] - v;
    if (t == CHUNK - 1) g_chunksum[b] = sm[t];
}

__global__ void scan2_kernel() {
    __shared__ int sm[128];
    int t = threadIdx.x;
    int v = (t < NB) ? g_chunksum[t] : 0;
    sm[t] = v;
    __syncthreads();
    for (int o = 1; o < 128; o <<= 1) {
        int add = (t >= o) ? sm[t - o] : 0;
        __syncthreads();
        sm[t] += add;
        __syncthreads();
    }
    if (t < NB) g_chunkoff[t] = sm[t] - v;
}

// Finalize rowptr/cursor; also computes inv_out.
__global__ void scan3_kernel() {
    int i = blockIdx.x * blockDim.x + threadIdx.x;
    if (i < NN) {
        int r = g_rowptr[i] + g_chunkoff[i / CHUNK];
        g_rowptr[i] = r;
        g_cursor[i] = r;
        g_inv_out[i] = rsqrtf(fmaxf((float)g_deg_out[i], 1.0f));
    }
    if (i == 0) g_rowptr[NN] = NE;
}

__global__ void bin_kernel(const int* __restrict__ src,
                           const int* __restrict__ dst) {
    int e = blockIdx.x * blockDim.x + threadIdx.x;
    if (e < NE) {
        int d = dst[e];
        int pos = atomicAdd(&g_cursor[d], 1);
        g_esrc[pos] = src[e];
    }
}

// h1 = (x * inv_out) @ W1  -> fp16 rows.
// 8 warps/block, 8 rows/warp, f32x2 dual-FMA.
__global__ void gemm1_kernel(const float* __restrict__ x,
                             const float* __restrict__ W1) {
    extern __shared__ float sm[];
    float* Wt = sm;                         // [32][WT_STRIDE]
    float* xs = sm + F1 * WT_STRIDE;        // [8 warps][8 rows][256]
    int tid = threadIdx.x;
    for (int i = tid; i < F0 * F1; i += blockDim.x) {
        int k = i >> 5, c = i & 31;
        Wt[c * WT_STRIDE + k] = W1[i];
    }
    __syncthreads();
    int warp = tid >> 5, lane = tid & 31;
    float* xw = xs + warp * (8 * F0);
    int base = blockIdx.x * 64 + warp * 8;

    #pragma unroll
    for (int r = 0; r < 8; r++) {
        int row = base + r;
        if (row >= NN) row = NN - 1;
        const float4* xr = (const float4*)(x + (size_t)row * F0);
        float4* dstp = (float4*)(xw + r * F0);
        dstp[lane]      = xr[lane];
        dstp[lane + 32] = xr[lane + 32];
    }
    __syncwarp();

    unsigned long long acc0 = 0ull, acc1 = 0ull, acc2 = 0ull, acc3 = 0ull;
    const float* wrow = Wt + lane * WT_STRIDE;

    #pragma unroll 4
    for (int kq = 0; kq < F0 / 4; kq++) {
        float4 w4 = *(const float4*)(wrow + kq * 4);
        unsigned long long wd0 = pack2(w4.x, w4.x);
        unsigned long long wd1 = pack2(w4.y, w4.y);
        unsigned long long wd2 = pack2(w4.z, w4.z);
        unsigned long long wd3 = pack2(w4.w, w4.w);
        {
            float4 xa = *(const float4*)(xw + 0 * F0 + kq * 4);
            float4 xb = *(const float4*)(xw + 1 * F0 + kq * 4);
            fma2(acc0, wd0, pack2(xa.x, xb.x));
            fma2(acc0, wd1, pack2(xa.y, xb.y));
            fma2(acc0, wd2, pack2(xa.z, xb.z));
            fma2(acc0, wd3, pack2(xa.w, xb.w));
        }
        {
            float4 xa = *(const float4*)(xw + 2 * F0 + kq * 4);
            float4 xb = *(const float4*)(xw + 3 * F0 + kq * 4);
            fma2(acc1, wd0, pack2(xa.x, xb.x));
            fma2(acc1, wd1, pack2(xa.y, xb.y));
            fma2(acc1, wd2, pack2(xa.z, xb.z));
            fma2(acc1, wd3, pack2(xa.w, xb.w));
        }
        {
            float4 xa = *(const float4*)(xw + 4 * F0 + kq * 4);
            float4 xb = *(const float4*)(xw + 5 * F0 + kq * 4);
            fma2(acc2, wd0, pack2(xa.x, xb.x));
            fma2(acc2, wd1, pack2(xa.y, xb.y));
            fma2(acc2, wd2, pack2(xa.z, xb.z));
            fma2(acc2, wd3, pack2(xa.w, xb.w));
        }
        {
            float4 xa = *(const float4*)(xw + 6 * F0 + kq * 4);
            float4 xb = *(const float4*)(xw + 7 * F0 + kq * 4);
            fma2(acc3, wd0, pack2(xa.x, xb.x));
            fma2(acc3, wd1, pack2(xa.y, xb.y));
            fma2(acc3, wd2, pack2(xa.z, xb.z));
            fma2(acc3, wd3, pack2(xa.w, xb.w));
        }
    }

    __half* h1h = (__half*)g_h1;
    unsigned long long accs[4] = {acc0, acc1, acc2, acc3};
    #pragma unroll
    for (int p = 0; p < 4; p++) {
        float2 v = unpack2(accs[p]);
        int r0 = base + 2 * p, r1 = r0 + 1;
        if (r0 < NN) h1h[r0 * F1 + lane] = __float2half_rn(v.x * g_inv_out[r0]);
        if (r1 < NN) h1h[r1 * F1 + lane] = __float2half_rn(v.y * g_inv_out[r1]);
    }
}

// agg1: warp-per-node, 2 edges per iteration (half-warp each), fp16 rows.
// lane = 16*slot + fp, fp covers feature pair (2fp, 2fp+1).
__global__ void agg1_kernel(const float* __restrict__ b1) {
    int gw = (blockIdx.x * blockDim.x + threadIdx.x) >> 5;
    int lane = threadIdx.x & 31;
    if (gw >= NN) return;
    int slot = lane >> 4, fp = lane & 15;
    int s = g_rowptr[gw], e = g_rowptr[gw + 1];

    float2 a0 = make_float2(0.f, 0.f), a1 = make_float2(0.f, 0.f);
    int j = s;
    for (; j + 2 < e; j += 4) {
        int jA = j + slot, jB = j + 2 + slot;
        int iA = __ldg(&g_esrc[jA]);
        float2 fA = __half22float2(g_h1[iA * 16 + fp]);
        a0.x += fA.x; a0.y += fA.y;
        if (jB < e) {
            int iB = __ldg(&g_esrc[jB]);
            float2 fB = __half22float2(g_h1[iB * 16 + fp]);
            a1.x += fB.x; a1.y += fB.y;
        }
    }
    for (; j < e; j += 2) {
        int jA = j + slot;
        if (jA < e) {
            int iA = __ldg(&g_esrc[jA]);
            float2 fA = __half22float2(g_h1[iA * 16 + fp]);
            a0.x += fA.x; a0.y += fA.y;
        }
    }
    float sx = a0.x + a1.x, sy = a0.y + a1.y;
    sx += __shfl_xor_sync(0xFFFFFFFFu, sx, 16);
    sy += __shfl_xor_sync(0xFFFFFFFFu, sy, 16);

    if (lane < 16) {
        float inv_i = g_inv_in[gw], inv_o = g_inv_out[gw];
        float v0 = sx * inv_i + b1[2 * fp];
        float v1 = sy * inv_i + b1[2 * fp + 1];
        v0 = (v0 > 0.f ? v0 : 0.f) * inv_o;
        v1 = (v1 > 0.f ? v1 : 0.f) * inv_o;
        g_hs[gw * 16 + fp] = __floats2half2_rn(v0, v1);
    }
}

// agg2 fused: gather hs (fp16), *inv_in, @W2 + b2, log_softmax, write out.
__global__ void agg2_kernel(const float* __restrict__ W2,
                            const float* __restrict__ b2,
                            float* __restrict__ out) {
    __shared__ float W2s[F1 * F2];   // 5 KB
    __shared__ float sa[8][F1];
    for (int i = threadIdx.x; i < F1 * F2; i += blockDim.x) W2s[i] = W2[i];
    __syncthreads();

    int gw = (blockIdx.x * blockDim.x + threadIdx.x) >> 5;
    int warp = threadIdx.x >> 5, lane = threadIdx.x & 31;
    if (gw >= NN) return;
    int slot = lane >> 4, fp = lane & 15;
    int s = g_rowptr[gw], e = g_rowptr[gw + 1];

    float2 a0 = make_float2(0.f, 0.f), a1 = make_float2(0.f, 0.f);
    int j = s;
    for (; j + 2 < e; j += 4) {
        int jA = j + slot, jB = j + 2 + slot;
        int iA = __ldg(&g_esrc[jA]);
        float2 fA = __half22float2(g_hs[iA * 16 + fp]);
        a0.x += fA.x; a0.y += fA.y;
        if (jB < e) {
            int iB = __ldg(&g_esrc[jB]);
            float2 fB = __half22float2(g_hs[iB * 16 + fp]);
            a1.x += fB.x; a1.y += fB.y;
        }
    }
    for (; j < e; j += 2) {
        int jA = j + slot;
        if (jA < e) {
            int iA = __ldg(&g_esrc[jA]);
            float2 fA = __half22float2(g_hs[iA * 16 + fp]);
            a0.x += fA.x; a0.y += fA.y;
        }
    }
    float sx = a0.x + a1.x, sy = a0.y + a1.y;
    sx += __shfl_xor_sync(0xFFFFFFFFu, sx, 16);
    sy += __shfl_xor_sync(0xFFFFFFFFu, sy, 16);

    float inv_i = g_inv_in[gw];
    if (lane < 16) {
        sa[warp][2 * fp]     = sx * inv_i;
        sa[warp][2 * fp + 1] = sy * inv_i;
    }
    __syncwarp();

    float v0 = b2[lane];
    float v1 = (lane < 8) ? b2[32 + lane] : -INFINITY;
    #pragma unroll
    for (int k = 0; k < F1; k++) {
        float ak = sa[warp][k];
        v0 = fmaf(ak, W2s[k * F2 + lane], v0);
        if (lane < 8) v1 = fmaf(ak, W2s[k * F2 + 32 + lane], v1);
    }

    float m = fmaxf(v0, v1);
    #pragma unroll
    for (int o = 16; o; o >>= 1) m = fmaxf(m, __shfl_xor_sync(0xFFFFFFFFu, m, o));
    float sum = expf(v0 - m) + ((lane < 8) ? expf(v1 - m) : 0.0f);
    #pragma unroll
    for (int o = 16; o; o >>= 1) sum += __shfl_xor_sync(0xFFFFFFFFu, sum, o);
    float L = m + logf(sum);
    out[gw * F2 + lane] = v0 - L;
    if (lane < 8) out[gw * F2 + 32 + lane] = v1 - L;
}

// ---------------- launcher ------------------------------------------------

extern "C" void kernel_launch(void* const* d_in, const int* in_sizes, int n_in,
                              void* d_out, int out_size) {
    const float* x   = (const float*)d_in[0];
    const float* W1  = (const float*)d_in[1];
    const float* b1  = (const float*)d_in[2];
    const float* W2  = (const float*)d_in[3];
    const float* b2  = (const float*)d_in[4];
    const int*   src = (const int*)d_in[5];
    const int*   dst = (const int*)d_in[6];
    float* out = (float*)d_out;

    const int TB = 256;
    int gN  = (NN + TB - 1) / TB;
    int gE  = (NE + TB - 1) / TB;
    int gWN = (NN * 32 + TB - 1) / TB;

    int g1_smem = (F1 * WT_STRIDE + 8 * 8 * F0) * (int)sizeof(float);  // 98816 B
    cudaFuncSetAttribute(gemm1_kernel,
                         cudaFuncAttributeMaxDynamicSharedMemorySize, g1_smem);

    zero_kernel<<<gN, TB>>>();
    degree_kernel<<<gE, TB>>>(src, dst);
    scan1_kernel<<<NB, CHUNK>>>();
    scan2_kernel<<<1, 128>>>();
    scan3_kernel<<<gN, TB>>>();
    bin_kernel<<<gE, TB>>>(src, dst);

    gemm1_kernel<<<G1_GROUPS, TB, g1_smem>>>(x, W1);
    agg1_kernel<<<gWN, TB>>>(b1);
    agg2_kernel<<<gWN, TB>>>(W2, b2, out);
}